// round 2
// baseline (speedup 1.0000x reference)
#include <cuda_runtime.h>
#include <stdint.h>

#define NN      16384
#define EE      524288
#define DD      128
#define HH      256
#define CC      10
#define GG      64
#define WPR     512          // bitmask words per row (16384/32)
#define CAP     160          // max neighbors per row

// ---------------- scratch (device globals; no allocation allowed) ----------------
__device__ uint32_t g_bm[(size_t)NN * WPR];        // 32 MB adjacency bitmask
__device__ int      g_nbr[(size_t)NN * CAP];       // CSR neighbor lists (sorted)
__device__ int      g_deg[NN];
__device__ float    g_dis[NN];
__device__ float    g_agg1[(size_t)NN * DD];
__device__ float    g_hd1 [(size_t)NN * HH];       // dis*relu(agg1@W1+b1)
__device__ float    g_agg2[(size_t)NN * HH];
__device__ float    g_h2  [(size_t)NN * HH];       // relu(agg2@W2+b2)
__device__ int      g_segstart[GG + 1];

// ---------------- helpers ----------------
__device__ __forceinline__ unsigned long long fma_f32x2(unsigned long long a,
                                                        unsigned long long b,
                                                        unsigned long long c) {
    unsigned long long d;
    asm("fma.rn.f32x2 %0, %1, %2, %3;" : "=l"(d) : "l"(a), "l"(b), "l"(c));
    return d;
}

// ---------------- kernels ----------------

__global__ void zero_bm_kernel() {
    const int n4 = NN * WPR / 4;
    uint4 z = make_uint4(0, 0, 0, 0);
    for (int i = blockIdx.x * blockDim.x + threadIdx.x; i < n4; i += gridDim.x * blockDim.x)
        reinterpret_cast<uint4*>(g_bm)[i] = z;
}

__global__ void scatter_kernel(const int* __restrict__ ei) {
    int idx = blockIdx.x * blockDim.x + threadIdx.x;
    if (idx < EE) {
        int s = ei[idx];
        int d = ei[EE + idx];
        atomicOr(&g_bm[(size_t)s * WPR + (d >> 5)], 1u << (d & 31));
    } else if (idx < EE + NN) {
        int i = idx - EE;
        atomicOr(&g_bm[(size_t)i * WPR + (i >> 5)], 1u << (i & 31));
    }
}

// warp per row: scan 512 bitmask words, emit sorted neighbor list + degree
__global__ void build_csr_kernel() {
    int wid  = (blockIdx.x * blockDim.x + threadIdx.x) >> 5;
    int lane = threadIdx.x & 31;
    if (wid >= NN) return;
    const uint32_t* row = g_bm + (size_t)wid * WPR;
    int* nbr = g_nbr + (size_t)wid * CAP;
    int cnt = 0;
    for (int w0 = 0; w0 < WPR; w0 += 32) {
        uint32_t bits = row[w0 + lane];
        int pc = __popc(bits);
        int incl = pc;
        #pragma unroll
        for (int o = 1; o < 32; o <<= 1) {
            int v = __shfl_up_sync(0xFFFFFFFFu, incl, o);
            if (lane >= o) incl += v;
        }
        int base = cnt + incl - pc;
        while (bits) {
            int b = __ffs(bits) - 1;
            bits &= bits - 1;
            if (base < CAP) nbr[base] = (w0 + lane) * 32 + b;
            base++;
        }
        cnt += __shfl_sync(0xFFFFFFFFu, incl, 31);
    }
    if (lane == 0) {
        int c = cnt < 1 ? 1 : cnt;
        g_deg[wid] = cnt < CAP ? cnt : CAP;
        g_dis[wid] = rsqrtf((float)c);
    }
}

// warp per row, D=128: lane handles one float4; dis[j] scaling fused in
__global__ void agg1_kernel(const float* __restrict__ x) {
    int row  = (blockIdx.x * blockDim.x + threadIdx.x) >> 5;
    int lane = threadIdx.x & 31;
    if (row >= NN) return;
    const float4* x4 = reinterpret_cast<const float4*>(x);
    const int* nbr = g_nbr + (size_t)row * CAP;
    int cnt = g_deg[row];
    float4 acc = make_float4(0.f, 0.f, 0.f, 0.f);
    for (int t0 = 0; t0 < cnt; t0 += 32) {
        int  j  = (t0 + lane < cnt) ? nbr[t0 + lane] : 0;
        float dj = g_dis[j];
        int m = min(32, cnt - t0);
        for (int k = 0; k < m; k++) {
            int   jj  = __shfl_sync(0xFFFFFFFFu, j, k);
            float djj = __shfl_sync(0xFFFFFFFFu, dj, k);
            float4 v = x4[(size_t)jj * 32 + lane];
            acc.x += djj * v.x; acc.y += djj * v.y; acc.z += djj * v.z; acc.w += djj * v.w;
        }
    }
    float s = g_dis[row];
    acc.x *= s; acc.y *= s; acc.z *= s; acc.w *= s;
    reinterpret_cast<float4*>(g_agg1)[(size_t)row * 32 + lane] = acc;
}

// warp per row, H=256: lane handles two float4 (hd1 already carries dis[j])
__global__ void agg2_kernel() {
    int row  = (blockIdx.x * blockDim.x + threadIdx.x) >> 5;
    int lane = threadIdx.x & 31;
    if (row >= NN) return;
    const float4* h4 = reinterpret_cast<const float4*>(g_hd1);
    const int* nbr = g_nbr + (size_t)row * CAP;
    int cnt = g_deg[row];
    float4 a0 = make_float4(0.f, 0.f, 0.f, 0.f);
    float4 a1 = make_float4(0.f, 0.f, 0.f, 0.f);
    for (int t0 = 0; t0 < cnt; t0 += 32) {
        int j = (t0 + lane < cnt) ? nbr[t0 + lane] : 0;
        int m = min(32, cnt - t0);
        for (int k = 0; k < m; k++) {
            int jj = __shfl_sync(0xFFFFFFFFu, j, k);
            float4 v0 = h4[(size_t)jj * 64 + lane];
            float4 v1 = h4[(size_t)jj * 64 + 32 + lane];
            a0.x += v0.x; a0.y += v0.y; a0.z += v0.z; a0.w += v0.w;
            a1.x += v1.x; a1.y += v1.y; a1.z += v1.z; a1.w += v1.w;
        }
    }
    float s = g_dis[row];
    a0.x *= s; a0.y *= s; a0.z *= s; a0.w *= s;
    a1.x *= s; a1.y *= s; a1.z *= s; a1.w *= s;
    float4* o4 = reinterpret_cast<float4*>(g_agg2);
    o4[(size_t)row * 64 + lane]      = a0;
    o4[(size_t)row * 64 + 32 + lane] = a1;
}

// ---------------- f32x2 GEMM: 128(M) x 256(N) tile, 512 threads, 8x8/thread ----------------
// A: [M,K] row-major, W: [K,256] row-major, C: [M,256]. KSTEP=16.
// A-tile stored in smem pre-duplicated as (a,a) float2 so the inner loop is pure fma.rn.f32x2.
template <int K, bool SCALE>
__device__ __forceinline__ void gemm_body(const float* __restrict__ A,
                                          const float* __restrict__ W,
                                          const float* __restrict__ bias,
                                          float* __restrict__ C) {
    __shared__ float2 AsD[16][128];   // 16 KB, duplicated pairs
    __shared__ float  Bs[16][256];    // 16 KB

    const int tid = threadIdx.x;
    const int tx = tid & 31;          // 32 col-groups
    const int ty = tid >> 5;          // 16 row-groups
    const int rowBase = blockIdx.x * 128;

    const int arow = tid >> 2;          // 0..127
    const int acol = (tid & 3) * 4;     // 0,4,8,12
    const int brow = tid >> 5;          // 0..15
    const int bcol = (tid & 31) * 4;    // 0..124

    unsigned long long acc[8][4];
    #pragma unroll
    for (int i = 0; i < 8; i++)
        #pragma unroll
        for (int j = 0; j < 4; j++) acc[i][j] = 0ull;

    for (int k0 = 0; k0 < K; k0 += 16) {
        float4 av = *reinterpret_cast<const float4*>(A + (size_t)(rowBase + arow) * K + k0 + acol);
        AsD[acol + 0][arow] = make_float2(av.x, av.x);
        AsD[acol + 1][arow] = make_float2(av.y, av.y);
        AsD[acol + 2][arow] = make_float2(av.z, av.z);
        AsD[acol + 3][arow] = make_float2(av.w, av.w);
        *reinterpret_cast<float4*>(&Bs[brow][bcol]) =
            *reinterpret_cast<const float4*>(W + (size_t)(k0 + brow) * 256 + bcol);
        *reinterpret_cast<float4*>(&Bs[brow][128 + bcol]) =
            *reinterpret_cast<const float4*>(W + (size_t)(k0 + brow) * 256 + 128 + bcol);
        __syncthreads();

        #pragma unroll
        for (int k = 0; k < 16; k++) {
            ulonglong2 a01 = *reinterpret_cast<const ulonglong2*>(&AsD[k][ty * 4]);
            ulonglong2 a23 = *reinterpret_cast<const ulonglong2*>(&AsD[k][ty * 4 + 2]);
            ulonglong2 a45 = *reinterpret_cast<const ulonglong2*>(&AsD[k][64 + ty * 4]);
            ulonglong2 a67 = *reinterpret_cast<const ulonglong2*>(&AsD[k][64 + ty * 4 + 2]);
            ulonglong2 b01 = *reinterpret_cast<const ulonglong2*>(&Bs[k][tx * 4]);
            ulonglong2 b23 = *reinterpret_cast<const ulonglong2*>(&Bs[k][128 + tx * 4]);
            unsigned long long a[8] = {a01.x, a01.y, a23.x, a23.y, a45.x, a45.y, a67.x, a67.y};
            unsigned long long b[4] = {b01.x, b01.y, b23.x, b23.y};
            #pragma unroll
            for (int i = 0; i < 8; i++)
                #pragma unroll
                for (int j = 0; j < 4; j++)
                    acc[i][j] = fma_f32x2(a[i], b[j], acc[i][j]);
        }
        __syncthreads();
    }

    #pragma unroll
    for (int i = 0; i < 8; i++) {
        int row = rowBase + ((i < 4) ? (ty * 4 + i) : (64 + ty * 4 + (i - 4)));
        float s = SCALE ? g_dis[row] : 1.f;
        #pragma unroll
        for (int jp = 0; jp < 4; jp++) {
            int col = (jp < 2) ? (tx * 4 + jp * 2) : (128 + tx * 4 + (jp - 2) * 2);
            union { unsigned long long u; float2 f; } cv;
            cv.u = acc[i][jp];
            float v0 = fmaxf(cv.f.x + bias[col],     0.f);
            float v1 = fmaxf(cv.f.y + bias[col + 1], 0.f);
            if (SCALE) { v0 *= s; v1 *= s; }
            *reinterpret_cast<float2*>(C + (size_t)row * 256 + col) = make_float2(v0, v1);
        }
    }
}

__global__ void __launch_bounds__(512) gemm1_kernel(const float* __restrict__ W1,
                                                    const float* __restrict__ b1) {
    gemm_body<DD, true>(g_agg1, W1, b1, g_hd1);
}

__global__ void __launch_bounds__(512) gemm2_kernel(const float* __restrict__ W2,
                                                    const float* __restrict__ b2) {
    gemm_body<HH, false>(g_agg2, W2, b2, g_h2);
}

__global__ void segstart_kernel(const int* __restrict__ batch) {
    int g = threadIdx.x;
    if (g > GG) return;
    if (g == GG) { g_segstart[GG] = NN; return; }
    int lo = 0, hi = NN;
    while (lo < hi) {
        int mid = (lo + hi) >> 1;
        if (batch[mid] < g) lo = mid + 1; else hi = mid;
    }
    g_segstart[g] = lo;
}

// block per graph: deterministic segment-mean + tiny classifier matvec
__global__ void __launch_bounds__(256) pool_classify_kernel(const float* __restrict__ Wc,
                                                            const float* __restrict__ bc,
                                                            float* __restrict__ out) {
    int g = blockIdx.x;
    int t = threadIdx.x;
    int s = g_segstart[g], e = g_segstart[g + 1];
    float sum = 0.f;
    for (int n = s; n < e; n++) sum += g_h2[(size_t)n * HH + t];
    float cnt = (float)max(e - s, 1);
    float pv = sum / cnt;

    float part[CC];
    const float* wr = Wc + t * CC;
    #pragma unroll
    for (int c = 0; c < CC; c++) part[c] = pv * wr[c];
    #pragma unroll
    for (int o = 16; o > 0; o >>= 1)
        #pragma unroll
        for (int c = 0; c < CC; c++) part[c] += __shfl_down_sync(0xFFFFFFFFu, part[c], o);

    __shared__ float red[8][CC];
    if ((t & 31) == 0)
        #pragma unroll
        for (int c = 0; c < CC; c++) red[t >> 5][c] = part[c];
    __syncthreads();
    if (t < CC) {
        float o = bc[t];
        #pragma unroll
        for (int w = 0; w < 8; w++) o += red[w][t];
        out[g * CC + t] = o;
    }
}

// ---------------- launch ----------------
extern "C" void kernel_launch(void* const* d_in, const int* in_sizes, int n_in,
                              void* d_out, int out_size) {
    const float* x   = (const float*)d_in[0];
    const int*   ei  = (const int*)  d_in[1];
    const int*   bat = (const int*)  d_in[2];
    const float* W1  = (const float*)d_in[3];
    const float* b1  = (const float*)d_in[4];
    const float* W2  = (const float*)d_in[5];
    const float* b2  = (const float*)d_in[6];
    const float* Wc  = (const float*)d_in[7];
    const float* bc  = (const float*)d_in[8];
    float* out = (float*)d_out;

    zero_bm_kernel<<<2048, 256>>>();
    scatter_kernel<<<(EE + NN + 255) / 256, 256>>>(ei);
    segstart_kernel<<<1, GG + 1>>>(bat);
    build_csr_kernel<<<NN / 8, 256>>>();
    agg1_kernel<<<NN / 8, 256>>>(x);
    gemm1_kernel<<<128, 512>>>(W1, b1);
    agg2_kernel<<<NN / 8, 256>>>();
    gemm2_kernel<<<128, 512>>>(W2, b2);
    pool_classify_kernel<<<GG, 256>>>(Wc, bc, out);
}

// round 3
// speedup vs baseline: 1.1601x; 1.1601x over previous
#include <cuda_runtime.h>
#include <cuda_fp16.h>
#include <stdint.h>

#define NN      16384
#define EE      524288
#define DD      128
#define HH      256
#define CC      10
#define GG      64
#define WPR     512          // bitmask words per row (16384/32)
#define CAP     160          // max neighbors per row

// ---------------- scratch (device globals; no allocation allowed) ----------------
__device__ uint32_t g_bm[(size_t)NN * WPR];        // 32 MB adjacency bitmask
__device__ int      g_nbr[(size_t)NN * CAP];       // CSR neighbor lists (unsorted)
__device__ int      g_deg[NN];
__device__ float    g_dis[NN];
__device__ __half   g_xh  [(size_t)NN * DD];       // half(dis[j]*x[j])
__device__ float    g_agg1[(size_t)NN * DD];
__device__ __half   g_hd1h[(size_t)NN * HH];       // half(dis*relu(agg1@W1+b1))
__device__ float    g_agg2[(size_t)NN * HH];
__device__ float    g_h2  [(size_t)NN * HH];       // relu(agg2@W2+b2)
__device__ int      g_segstart[GG + 1];

// ---------------- helpers ----------------
__device__ __forceinline__ unsigned long long fma_f32x2(unsigned long long a,
                                                        unsigned long long b,
                                                        unsigned long long c) {
    unsigned long long d;
    asm("fma.rn.f32x2 %0, %1, %2, %3;" : "=l"(d) : "l"(a), "l"(b), "l"(c));
    return d;
}

// ---------------- kernels ----------------

__global__ void zero_bm_kernel() {
    const int n4 = NN * WPR / 4;
    uint4 z = make_uint4(0, 0, 0, 0);
    for (int i = blockIdx.x * blockDim.x + threadIdx.x; i < n4; i += gridDim.x * blockDim.x)
        reinterpret_cast<uint4*>(g_bm)[i] = z;
}

__global__ void scatter_kernel(const int* __restrict__ ei) {
    int idx = blockIdx.x * blockDim.x + threadIdx.x;
    if (idx < EE) {
        int s = ei[idx];
        int d = ei[EE + idx];
        atomicOr(&g_bm[(size_t)s * WPR + (d >> 5)], 1u << (d & 31));
    } else if (idx < EE + NN) {
        int i = idx - EE;
        atomicOr(&g_bm[(size_t)i * WPR + (i >> 5)], 1u << (i & 31));
    }
}

// warp per row: lane owns 16 contiguous words; ONE warp prefix-sum; emit
// neighbors (unsorted across lanes — accumulation order is irrelevant).
__global__ void build_csr_kernel() {
    int wid  = (blockIdx.x * blockDim.x + threadIdx.x) >> 5;
    int lane = threadIdx.x & 31;
    if (wid >= NN) return;
    const uint4* row4 = reinterpret_cast<const uint4*>(g_bm + (size_t)wid * WPR) + lane * 4;
    uint4 w[4];
    int cnt = 0;
    #pragma unroll
    for (int i = 0; i < 4; i++) {
        w[i] = row4[i];
        cnt += __popc(w[i].x) + __popc(w[i].y) + __popc(w[i].z) + __popc(w[i].w);
    }
    int incl = cnt;
    #pragma unroll
    for (int o = 1; o < 32; o <<= 1) {
        int v = __shfl_up_sync(0xFFFFFFFFu, incl, o);
        if (lane >= o) incl += v;
    }
    int total = __shfl_sync(0xFFFFFFFFu, incl, 31);
    int base = incl - cnt;
    int* nbr = g_nbr + (size_t)wid * CAP;
    int bitbase = lane * 512;   // lane*16 words * 32 bits
    #pragma unroll
    for (int i = 0; i < 4; i++) {
        uint32_t ws[4] = {w[i].x, w[i].y, w[i].z, w[i].w};
        #pragma unroll
        for (int q = 0; q < 4; q++) {
            uint32_t bits = ws[q];
            int bb = bitbase + (i * 4 + q) * 32;
            while (bits) {
                int b = __ffs(bits) - 1;
                bits &= bits - 1;
                if (base < CAP) nbr[base] = bb + b;
                base++;
            }
        }
    }
    if (lane == 0) {
        int c = total < 1 ? 1 : total;
        g_deg[wid] = total < CAP ? total : CAP;
        g_dis[wid] = rsqrtf((float)c);
    }
}

// xh[n][f] = half(dis[n] * x[n][f]); grid-stride over half2 elements
__global__ void convert_x_kernel(const float* __restrict__ x) {
    const int n2 = NN * DD / 2;   // half2 count; 64 per row
    const float2* x2 = reinterpret_cast<const float2*>(x);
    __half2* o2 = reinterpret_cast<__half2*>(g_xh);
    for (int i = blockIdx.x * blockDim.x + threadIdx.x; i < n2; i += gridDim.x * blockDim.x) {
        float s = g_dis[i >> 6];
        float2 v = x2[i];
        o2[i] = __float22half2_rn(make_float2(v.x * s, v.y * s));
    }
}

// warp per row, D=128: lane handles 4 halves (8B load per neighbor)
__global__ void agg1_kernel() {
    int row  = (blockIdx.x * blockDim.x + threadIdx.x) >> 5;
    int lane = threadIdx.x & 31;
    if (row >= NN) return;
    const int* nbr = g_nbr + (size_t)row * CAP;
    int cnt = g_deg[row];
    float4 acc = make_float4(0.f, 0.f, 0.f, 0.f);
    for (int t0 = 0; t0 < cnt; t0 += 32) {
        int j = (t0 + lane < cnt) ? nbr[t0 + lane] : 0;
        int m = min(32, cnt - t0);
        for (int k = 0; k < m; k++) {
            int jj = __shfl_sync(0xFFFFFFFFu, j, k);
            uint2 raw = *reinterpret_cast<const uint2*>(g_xh + (size_t)jj * DD + lane * 4);
            float2 f0 = __half22float2(*reinterpret_cast<__half2*>(&raw.x));
            float2 f1 = __half22float2(*reinterpret_cast<__half2*>(&raw.y));
            acc.x += f0.x; acc.y += f0.y; acc.z += f1.x; acc.w += f1.y;
        }
    }
    float s = g_dis[row];
    acc.x *= s; acc.y *= s; acc.z *= s; acc.w *= s;
    float4* o4 = reinterpret_cast<float4*>(g_agg1);
    // feature layout: lane*4 .. lane*4+3  -> float4 index lane
    o4[(size_t)row * 32 + lane] = acc;
}

// warp per row, H=256: lane handles 8 halves (16B load per neighbor)
__global__ void agg2_kernel() {
    int row  = (blockIdx.x * blockDim.x + threadIdx.x) >> 5;
    int lane = threadIdx.x & 31;
    if (row >= NN) return;
    const int* nbr = g_nbr + (size_t)row * CAP;
    int cnt = g_deg[row];
    float4 a0 = make_float4(0.f, 0.f, 0.f, 0.f);
    float4 a1 = make_float4(0.f, 0.f, 0.f, 0.f);
    for (int t0 = 0; t0 < cnt; t0 += 32) {
        int j = (t0 + lane < cnt) ? nbr[t0 + lane] : 0;
        int m = min(32, cnt - t0);
        for (int k = 0; k < m; k++) {
            int jj = __shfl_sync(0xFFFFFFFFu, j, k);
            uint4 raw = *reinterpret_cast<const uint4*>(g_hd1h + (size_t)jj * HH + lane * 8);
            float2 f0 = __half22float2(*reinterpret_cast<__half2*>(&raw.x));
            float2 f1 = __half22float2(*reinterpret_cast<__half2*>(&raw.y));
            float2 f2 = __half22float2(*reinterpret_cast<__half2*>(&raw.z));
            float2 f3 = __half22float2(*reinterpret_cast<__half2*>(&raw.w));
            a0.x += f0.x; a0.y += f0.y; a0.z += f1.x; a0.w += f1.y;
            a1.x += f2.x; a1.y += f2.y; a1.z += f3.x; a1.w += f3.y;
        }
    }
    float s = g_dis[row];
    a0.x *= s; a0.y *= s; a0.z *= s; a0.w *= s;
    a1.x *= s; a1.y *= s; a1.z *= s; a1.w *= s;
    // feature layout: lane*8 .. lane*8+7 -> float4 indices 2*lane, 2*lane+1
    float4* o4 = reinterpret_cast<float4*>(g_agg2);
    o4[(size_t)row * 64 + lane * 2]     = a0;
    o4[(size_t)row * 64 + lane * 2 + 1] = a1;
}

// ---------------- f32x2 GEMM: 128(M) x 256(N) tile, 512 threads, 8x8/thread ----------------
// OUT_HALF: epilogue writes __half (with dis scale) to Ch; else fp32 to Cf.
template <int K, bool SCALE, bool OUT_HALF>
__device__ __forceinline__ void gemm_body(const float* __restrict__ A,
                                          const float* __restrict__ W,
                                          const float* __restrict__ bias,
                                          float* __restrict__ Cf,
                                          __half* __restrict__ Ch) {
    __shared__ float2 AsD[16][128];   // duplicated (a,a) pairs
    __shared__ float  Bs[16][256];

    const int tid = threadIdx.x;
    const int tx = tid & 31;
    const int ty = tid >> 5;
    const int rowBase = blockIdx.x * 128;

    const int arow = tid >> 2;
    const int acol = (tid & 3) * 4;
    const int brow = tid >> 5;
    const int bcol = (tid & 31) * 4;

    unsigned long long acc[8][4];
    #pragma unroll
    for (int i = 0; i < 8; i++)
        #pragma unroll
        for (int j = 0; j < 4; j++) acc[i][j] = 0ull;

    for (int k0 = 0; k0 < K; k0 += 16) {
        float4 av = *reinterpret_cast<const float4*>(A + (size_t)(rowBase + arow) * K + k0 + acol);
        AsD[acol + 0][arow] = make_float2(av.x, av.x);
        AsD[acol + 1][arow] = make_float2(av.y, av.y);
        AsD[acol + 2][arow] = make_float2(av.z, av.z);
        AsD[acol + 3][arow] = make_float2(av.w, av.w);
        *reinterpret_cast<float4*>(&Bs[brow][bcol]) =
            *reinterpret_cast<const float4*>(W + (size_t)(k0 + brow) * 256 + bcol);
        *reinterpret_cast<float4*>(&Bs[brow][128 + bcol]) =
            *reinterpret_cast<const float4*>(W + (size_t)(k0 + brow) * 256 + 128 + bcol);
        __syncthreads();

        #pragma unroll
        for (int k = 0; k < 16; k++) {
            ulonglong2 a01 = *reinterpret_cast<const ulonglong2*>(&AsD[k][ty * 4]);
            ulonglong2 a23 = *reinterpret_cast<const ulonglong2*>(&AsD[k][ty * 4 + 2]);
            ulonglong2 a45 = *reinterpret_cast<const ulonglong2*>(&AsD[k][64 + ty * 4]);
            ulonglong2 a67 = *reinterpret_cast<const ulonglong2*>(&AsD[k][64 + ty * 4 + 2]);
            ulonglong2 b01 = *reinterpret_cast<const ulonglong2*>(&Bs[k][tx * 4]);
            ulonglong2 b23 = *reinterpret_cast<const ulonglong2*>(&Bs[k][128 + tx * 4]);
            unsigned long long a[8] = {a01.x, a01.y, a23.x, a23.y, a45.x, a45.y, a67.x, a67.y};
            unsigned long long b[4] = {b01.x, b01.y, b23.x, b23.y};
            #pragma unroll
            for (int i = 0; i < 8; i++)
                #pragma unroll
                for (int j = 0; j < 4; j++)
                    acc[i][j] = fma_f32x2(a[i], b[j], acc[i][j]);
        }
        __syncthreads();
    }

    #pragma unroll
    for (int i = 0; i < 8; i++) {
        int row = rowBase + ((i < 4) ? (ty * 4 + i) : (64 + ty * 4 + (i - 4)));
        float s = SCALE ? g_dis[row] : 1.f;
        #pragma unroll
        for (int jp = 0; jp < 4; jp++) {
            int col = (jp < 2) ? (tx * 4 + jp * 2) : (128 + tx * 4 + (jp - 2) * 2);
            union { unsigned long long u; float2 f; } cv;
            cv.u = acc[i][jp];
            float v0 = fmaxf(cv.f.x + bias[col],     0.f);
            float v1 = fmaxf(cv.f.y + bias[col + 1], 0.f);
            if (SCALE) { v0 *= s; v1 *= s; }
            if (OUT_HALF) {
                *reinterpret_cast<__half2*>(Ch + (size_t)row * 256 + col) =
                    __float22half2_rn(make_float2(v0, v1));
            } else {
                *reinterpret_cast<float2*>(Cf + (size_t)row * 256 + col) = make_float2(v0, v1);
            }
        }
    }
}

__global__ void __launch_bounds__(512) gemm1_kernel(const float* __restrict__ W1,
                                                    const float* __restrict__ b1) {
    gemm_body<DD, true, true>(g_agg1, W1, b1, nullptr, g_hd1h);
}

__global__ void __launch_bounds__(512) gemm2_kernel(const float* __restrict__ W2,
                                                    const float* __restrict__ b2) {
    gemm_body<HH, false, false>(g_agg2, W2, b2, g_h2, nullptr);
}

__global__ void segstart_kernel(const int* __restrict__ batch) {
    int g = threadIdx.x;
    if (g > GG) return;
    if (g == GG) { g_segstart[GG] = NN; return; }
    int lo = 0, hi = NN;
    while (lo < hi) {
        int mid = (lo + hi) >> 1;
        if (batch[mid] < g) lo = mid + 1; else hi = mid;
    }
    g_segstart[g] = lo;
}

// block per graph: deterministic segment-mean + tiny classifier matvec
__global__ void __launch_bounds__(256) pool_classify_kernel(const float* __restrict__ Wc,
                                                            const float* __restrict__ bc,
                                                            float* __restrict__ out) {
    int g = blockIdx.x;
    int t = threadIdx.x;
    int s = g_segstart[g], e = g_segstart[g + 1];
    float sum = 0.f;
    for (int n = s; n < e; n++) sum += g_h2[(size_t)n * HH + t];
    float cnt = (float)max(e - s, 1);
    float pv = sum / cnt;

    float part[CC];
    const float* wr = Wc + t * CC;
    #pragma unroll
    for (int c = 0; c < CC; c++) part[c] = pv * wr[c];
    #pragma unroll
    for (int o = 16; o > 0; o >>= 1)
        #pragma unroll
        for (int c = 0; c < CC; c++) part[c] += __shfl_down_sync(0xFFFFFFFFu, part[c], o);

    __shared__ float red[8][CC];
    if ((t & 31) == 0)
        #pragma unroll
        for (int c = 0; c < CC; c++) red[t >> 5][c] = part[c];
    __syncthreads();
    if (t < CC) {
        float o = bc[t];
        #pragma unroll
        for (int w = 0; w < 8; w++) o += red[w][t];
        out[g * CC + t] = o;
    }
}

// ---------------- launch ----------------
extern "C" void kernel_launch(void* const* d_in, const int* in_sizes, int n_in,
                              void* d_out, int out_size) {
    const float* x   = (const float*)d_in[0];
    const int*   ei  = (const int*)  d_in[1];
    const int*   bat = (const int*)  d_in[2];
    const float* W1  = (const float*)d_in[3];
    const float* b1  = (const float*)d_in[4];
    const float* W2  = (const float*)d_in[5];
    const float* b2  = (const float*)d_in[6];
    const float* Wc  = (const float*)d_in[7];
    const float* bc  = (const float*)d_in[8];
    float* out = (float*)d_out;

    zero_bm_kernel<<<2048, 256>>>();
    scatter_kernel<<<(EE + NN + 255) / 256, 256>>>(ei);
    segstart_kernel<<<1, GG + 1>>>(bat);
    build_csr_kernel<<<NN / 8, 256>>>();
    convert_x_kernel<<<2048, 256>>>(x);
    agg1_kernel<<<NN / 8, 256>>>();
    gemm1_kernel<<<128, 512>>>(W1, b1);
    agg2_kernel<<<NN / 8, 256>>>();
    gemm2_kernel<<<128, 512>>>(W2, b2);
    pool_classify_kernel<<<GG, 256>>>(Wc, bc, out);
}

// round 4
// speedup vs baseline: 1.8075x; 1.5580x over previous
#include <cuda_runtime.h>
#include <cuda_fp16.h>
#include <stdint.h>

#define NN      16384
#define EE      524288
#define DD      128
#define HH      256
#define CC      10
#define GG      64
#define WPR     512          // bitmask words per row (16384/32)
#define CAP     160          // max neighbors per row

// ---------------- scratch (device globals; no allocation allowed) ----------------
__device__ uint32_t g_bm[(size_t)NN * WPR];        // 32 MB adjacency bitmask
__device__ int      g_nbr[(size_t)NN * CAP];       // CSR neighbor lists (unsorted)
__device__ int      g_deg[NN];
__device__ float    g_dis[NN];
__device__ __half   g_xh   [(size_t)NN * DD];      // half(dis[j]*x[j])
__device__ __half   g_agg1h[(size_t)NN * DD];      // half(dis[i]*sum)
__device__ __half   g_hd1h [(size_t)NN * HH];      // half(dis*relu(.@W1+b1))
__device__ __half   g_agg2h[(size_t)NN * HH];
__device__ float    g_h2   [(size_t)NN * HH];      // relu(.@W2+b2)
__device__ __half   g_w1h[DD * HH];
__device__ __half   g_w2h[HH * HH];
__device__ int      g_segstart[GG + 1];

// ---------------- mma helpers ----------------
__device__ __forceinline__ uint32_t cvta_smem(const void* p) {
    return static_cast<uint32_t>(__cvta_generic_to_shared(p));
}
__device__ __forceinline__ void ldsm_x4(uint32_t (&r)[4], uint32_t addr) {
    asm volatile("ldmatrix.sync.aligned.m8n8.x4.shared.b16 {%0,%1,%2,%3}, [%4];"
                 : "=r"(r[0]), "=r"(r[1]), "=r"(r[2]), "=r"(r[3]) : "r"(addr));
}
__device__ __forceinline__ void ldsm_x4_t(uint32_t (&r)[4], uint32_t addr) {
    asm volatile("ldmatrix.sync.aligned.m8n8.x4.trans.shared.b16 {%0,%1,%2,%3}, [%4];"
                 : "=r"(r[0]), "=r"(r[1]), "=r"(r[2]), "=r"(r[3]) : "r"(addr));
}
__device__ __forceinline__ void mma16816(float (&d)[4], const uint32_t (&a)[4],
                                         const uint32_t b0, const uint32_t b1) {
    asm volatile("mma.sync.aligned.m16n8k16.row.col.f32.f16.f16.f32 "
                 "{%0,%1,%2,%3},{%4,%5,%6,%7},{%8,%9},{%0,%1,%2,%3};"
                 : "+f"(d[0]), "+f"(d[1]), "+f"(d[2]), "+f"(d[3])
                 : "r"(a[0]), "r"(a[1]), "r"(a[2]), "r"(a[3]), "r"(b0), "r"(b1));
}

// ---------------- setup kernels ----------------

__global__ void zero_bm_kernel() {
    const int n4 = NN * WPR / 4;
    uint4 z = make_uint4(0, 0, 0, 0);
    for (int i = blockIdx.x * blockDim.x + threadIdx.x; i < n4; i += gridDim.x * blockDim.x)
        reinterpret_cast<uint4*>(g_bm)[i] = z;
}

__global__ void scatter_kernel(const int* __restrict__ ei) {
    int idx = blockIdx.x * blockDim.x + threadIdx.x;
    if (idx < EE) {
        int s = ei[idx];
        int d = ei[EE + idx];
        atomicOr(&g_bm[(size_t)s * WPR + (d >> 5)], 1u << (d & 31));
    } else if (idx < EE + NN) {
        int i = idx - EE;
        atomicOr(&g_bm[(size_t)i * WPR + (i >> 5)], 1u << (i & 31));
    }
}

// warp per row: lane owns 16 contiguous words; one warp prefix-sum; emit unsorted
__global__ void build_csr_kernel() {
    int wid  = (blockIdx.x * blockDim.x + threadIdx.x) >> 5;
    int lane = threadIdx.x & 31;
    if (wid >= NN) return;
    const uint4* row4 = reinterpret_cast<const uint4*>(g_bm + (size_t)wid * WPR) + lane * 4;
    uint4 w[4];
    int cnt = 0;
    #pragma unroll
    for (int i = 0; i < 4; i++) {
        w[i] = row4[i];
        cnt += __popc(w[i].x) + __popc(w[i].y) + __popc(w[i].z) + __popc(w[i].w);
    }
    int incl = cnt;
    #pragma unroll
    for (int o = 1; o < 32; o <<= 1) {
        int v = __shfl_up_sync(0xFFFFFFFFu, incl, o);
        if (lane >= o) incl += v;
    }
    int total = __shfl_sync(0xFFFFFFFFu, incl, 31);
    int base = incl - cnt;
    int* nbr = g_nbr + (size_t)wid * CAP;
    int bitbase = lane * 512;
    #pragma unroll
    for (int i = 0; i < 4; i++) {
        uint32_t ws[4] = {w[i].x, w[i].y, w[i].z, w[i].w};
        #pragma unroll
        for (int q = 0; q < 4; q++) {
            uint32_t bits = ws[q];
            int bb = bitbase + (i * 4 + q) * 32;
            while (bits) {
                int b = __ffs(bits) - 1;
                bits &= bits - 1;
                if (base < CAP) nbr[base] = bb + b;
                base++;
            }
        }
    }
    if (lane == 0) {
        int c = total < 1 ? 1 : total;
        g_deg[wid] = total < CAP ? total : CAP;
        g_dis[wid] = rsqrtf((float)c);
    }
}

// xh[n][f] = half(dis[n]*x[n][f])
__global__ void convert_x_kernel(const float* __restrict__ x) {
    const int n2 = NN * DD / 2;
    const float2* x2 = reinterpret_cast<const float2*>(x);
    __half2* o2 = reinterpret_cast<__half2*>(g_xh);
    for (int i = blockIdx.x * blockDim.x + threadIdx.x; i < n2; i += gridDim.x * blockDim.x) {
        float s = g_dis[i >> 6];
        float2 v = x2[i];
        o2[i] = __float22half2_rn(make_float2(v.x * s, v.y * s));
    }
}

__global__ void convert_w_kernel(const float* __restrict__ W1, const float* __restrict__ W2) {
    int i = blockIdx.x * blockDim.x + threadIdx.x;
    if (i < DD * HH) g_w1h[i] = __float2half_rn(W1[i]);
    int j = i - DD * HH;
    if (j >= 0 && j < HH * HH) g_w2h[j] = __float2half_rn(W2[j]);
}

// ---------------- gathers ----------------

// warp per row, D=128: lane handles 4 halves; output fp16
__global__ void agg1_kernel() {
    int row  = (blockIdx.x * blockDim.x + threadIdx.x) >> 5;
    int lane = threadIdx.x & 31;
    if (row >= NN) return;
    const int* nbr = g_nbr + (size_t)row * CAP;
    int cnt = g_deg[row];
    float4 acc = make_float4(0.f, 0.f, 0.f, 0.f);
    for (int t0 = 0; t0 < cnt; t0 += 32) {
        int j = (t0 + lane < cnt) ? nbr[t0 + lane] : 0;
        int m = min(32, cnt - t0);
        for (int k = 0; k < m; k++) {
            int jj = __shfl_sync(0xFFFFFFFFu, j, k);
            uint2 raw = *reinterpret_cast<const uint2*>(g_xh + (size_t)jj * DD + lane * 4);
            float2 f0 = __half22float2(*reinterpret_cast<__half2*>(&raw.x));
            float2 f1 = __half22float2(*reinterpret_cast<__half2*>(&raw.y));
            acc.x += f0.x; acc.y += f0.y; acc.z += f1.x; acc.w += f1.y;
        }
    }
    float s = g_dis[row];
    __half2 h0 = __float22half2_rn(make_float2(acc.x * s, acc.y * s));
    __half2 h1 = __float22half2_rn(make_float2(acc.z * s, acc.w * s));
    uint2 packed = make_uint2(*reinterpret_cast<uint32_t*>(&h0), *reinterpret_cast<uint32_t*>(&h1));
    *reinterpret_cast<uint2*>(g_agg1h + (size_t)row * DD + lane * 4) = packed;
}

// warp per row, H=256: lane handles 8 halves; output fp16
__global__ void agg2_kernel() {
    int row  = (blockIdx.x * blockDim.x + threadIdx.x) >> 5;
    int lane = threadIdx.x & 31;
    if (row >= NN) return;
    const int* nbr = g_nbr + (size_t)row * CAP;
    int cnt = g_deg[row];
    float4 a0 = make_float4(0.f, 0.f, 0.f, 0.f);
    float4 a1 = make_float4(0.f, 0.f, 0.f, 0.f);
    for (int t0 = 0; t0 < cnt; t0 += 32) {
        int j = (t0 + lane < cnt) ? nbr[t0 + lane] : 0;
        int m = min(32, cnt - t0);
        for (int k = 0; k < m; k++) {
            int jj = __shfl_sync(0xFFFFFFFFu, j, k);
            uint4 raw = *reinterpret_cast<const uint4*>(g_hd1h + (size_t)jj * HH + lane * 8);
            float2 f0 = __half22float2(*reinterpret_cast<__half2*>(&raw.x));
            float2 f1 = __half22float2(*reinterpret_cast<__half2*>(&raw.y));
            float2 f2 = __half22float2(*reinterpret_cast<__half2*>(&raw.z));
            float2 f3 = __half22float2(*reinterpret_cast<__half2*>(&raw.w));
            a0.x += f0.x; a0.y += f0.y; a0.z += f1.x; a0.w += f1.y;
            a1.x += f2.x; a1.y += f2.y; a1.z += f3.x; a1.w += f3.y;
        }
    }
    float s = g_dis[row];
    __half2 h0 = __float22half2_rn(make_float2(a0.x * s, a0.y * s));
    __half2 h1 = __float22half2_rn(make_float2(a0.z * s, a0.w * s));
    __half2 h2 = __float22half2_rn(make_float2(a1.x * s, a1.y * s));
    __half2 h3 = __float22half2_rn(make_float2(a1.z * s, a1.w * s));
    uint4 packed = make_uint4(*reinterpret_cast<uint32_t*>(&h0), *reinterpret_cast<uint32_t*>(&h1),
                              *reinterpret_cast<uint32_t*>(&h2), *reinterpret_cast<uint32_t*>(&h3));
    *reinterpret_cast<uint4*>(g_agg2h + (size_t)row * HH + lane * 8) = packed;
}

// ---------------- HMMA GEMM: 128x128 CTA tile, 8 warps (32x64 each), BK=32 ----------------
// A [M,K] fp16 row-major, W [K,256] fp16 row-major. Epilogue: bias+relu (+dis scale).
template <int K, bool SCALE, bool OUT_HALF>
__global__ void __launch_bounds__(256, 2) hgemm_kernel(const __half* __restrict__ A,
                                                       const __half* __restrict__ W,
                                                       const float* __restrict__ bias,
                                                       float* __restrict__ Cf,
                                                       __half* __restrict__ Ch) {
    __shared__ __half As[128][40];    // 32 + 8 pad
    __shared__ __half Bs[32][136];    // 128 + 8 pad

    const int tid  = threadIdx.x;
    const int lane = tid & 31;
    const int warp = tid >> 5;
    const int wm = warp & 3;          // 4 warps along M
    const int wn = warp >> 2;         // 2 warps along N
    const int rowBase = blockIdx.y * 128;
    const int colBase = blockIdx.x * 128;

    float acc[2][8][4];
    #pragma unroll
    for (int f = 0; f < 2; f++)
        #pragma unroll
        for (int t = 0; t < 8; t++)
            #pragma unroll
            for (int c = 0; c < 4; c++) acc[f][t][c] = 0.f;

    const int ar = tid >> 1, ac = (tid & 1) * 16;
    const int br = tid >> 3, bc = (tid & 7) * 16;

    for (int k0 = 0; k0 < K; k0 += 32) {
        const __half* ag = A + (size_t)(rowBase + ar) * K + k0 + ac;
        *reinterpret_cast<uint4*>(&As[ar][ac])     = *reinterpret_cast<const uint4*>(ag);
        *reinterpret_cast<uint4*>(&As[ar][ac + 8]) = *reinterpret_cast<const uint4*>(ag + 8);
        const __half* bg = W + (size_t)(k0 + br) * 256 + colBase + bc;
        *reinterpret_cast<uint4*>(&Bs[br][bc])     = *reinterpret_cast<const uint4*>(bg);
        *reinterpret_cast<uint4*>(&Bs[br][bc + 8]) = *reinterpret_cast<const uint4*>(bg + 8);
        __syncthreads();

        #pragma unroll
        for (int kk = 0; kk < 32; kk += 16) {
            uint32_t afr[2][4];
            #pragma unroll
            for (int f = 0; f < 2; f++)
                ldsm_x4(afr[f], cvta_smem(&As[wm * 32 + f * 16 + (lane & 15)][kk + (lane >> 4) * 8]));
            uint32_t bfr[8][2];
            #pragma unroll
            for (int g = 0; g < 4; g++) {
                uint32_t t4[4];
                ldsm_x4_t(t4, cvta_smem(&Bs[kk + (lane & 15)][wn * 64 + g * 16 + (lane >> 4) * 8]));
                bfr[2 * g][0] = t4[0]; bfr[2 * g][1] = t4[1];
                bfr[2 * g + 1][0] = t4[2]; bfr[2 * g + 1][1] = t4[3];
            }
            #pragma unroll
            for (int f = 0; f < 2; f++)
                #pragma unroll
                for (int t = 0; t < 8; t++)
                    mma16816(acc[f][t], afr[f], bfr[t][0], bfr[t][1]);
        }
        __syncthreads();
    }

    #pragma unroll
    for (int f = 0; f < 2; f++) {
        #pragma unroll
        for (int t = 0; t < 8; t++) {
            int r0  = rowBase + wm * 32 + f * 16 + (lane >> 2);
            int col = colBase + wn * 64 + t * 8 + (lane & 3) * 2;
            float b0 = bias[col], b1 = bias[col + 1];
            #pragma unroll
            for (int h = 0; h < 2; h++) {
                int row = r0 + h * 8;
                float v0 = fmaxf(acc[f][t][h * 2 + 0] + b0, 0.f);
                float v1 = fmaxf(acc[f][t][h * 2 + 1] + b1, 0.f);
                if (SCALE) { float s = g_dis[row]; v0 *= s; v1 *= s; }
                if (OUT_HALF) {
                    *reinterpret_cast<__half2*>(Ch + (size_t)row * 256 + col) =
                        __float22half2_rn(make_float2(v0, v1));
                } else {
                    *reinterpret_cast<float2*>(Cf + (size_t)row * 256 + col) = make_float2(v0, v1);
                }
            }
        }
    }
}

// ---------------- pooling / classifier ----------------

__global__ void segstart_kernel(const int* __restrict__ batch) {
    int g = threadIdx.x;
    if (g > GG) return;
    if (g == GG) { g_segstart[GG] = NN; return; }
    int lo = 0, hi = NN;
    while (lo < hi) {
        int mid = (lo + hi) >> 1;
        if (batch[mid] < g) lo = mid + 1; else hi = mid;
    }
    g_segstart[g] = lo;
}

__global__ void __launch_bounds__(256) pool_classify_kernel(const float* __restrict__ Wc,
                                                            const float* __restrict__ bc,
                                                            float* __restrict__ out) {
    int g = blockIdx.x;
    int t = threadIdx.x;
    int s = g_segstart[g], e = g_segstart[g + 1];
    float sum = 0.f;
    for (int n = s; n < e; n++) sum += g_h2[(size_t)n * HH + t];
    float cnt = (float)max(e - s, 1);
    float pv = sum / cnt;

    float part[CC];
    const float* wr = Wc + t * CC;
    #pragma unroll
    for (int c = 0; c < CC; c++) part[c] = pv * wr[c];
    #pragma unroll
    for (int o = 16; o > 0; o >>= 1)
        #pragma unroll
        for (int c = 0; c < CC; c++) part[c] += __shfl_down_sync(0xFFFFFFFFu, part[c], o);

    __shared__ float red[8][CC];
    if ((t & 31) == 0)
        #pragma unroll
        for (int c = 0; c < CC; c++) red[t >> 5][c] = part[c];
    __syncthreads();
    if (t < CC) {
        float o = bc[t];
        #pragma unroll
        for (int w = 0; w < 8; w++) o += red[w][t];
        out[g * CC + t] = o;
    }
}

// ---------------- launch ----------------
extern "C" void kernel_launch(void* const* d_in, const int* in_sizes, int n_in,
                              void* d_out, int out_size) {
    const float* x   = (const float*)d_in[0];
    const int*   ei  = (const int*)  d_in[1];
    const int*   bat = (const int*)  d_in[2];
    const float* W1  = (const float*)d_in[3];
    const float* b1  = (const float*)d_in[4];
    const float* W2  = (const float*)d_in[5];
    const float* b2  = (const float*)d_in[6];
    const float* Wc  = (const float*)d_in[7];
    const float* bc  = (const float*)d_in[8];
    float* out = (float*)d_out;

    __half *w1h, *w2h, *agg1h, *agg2h, *hd1h;
    float* h2;
    cudaGetSymbolAddress((void**)&w1h,  g_w1h);
    cudaGetSymbolAddress((void**)&w2h,  g_w2h);
    cudaGetSymbolAddress((void**)&agg1h, g_agg1h);
    cudaGetSymbolAddress((void**)&agg2h, g_agg2h);
    cudaGetSymbolAddress((void**)&hd1h,  g_hd1h);
    cudaGetSymbolAddress((void**)&h2,    g_h2);

    zero_bm_kernel<<<2048, 256>>>();
    scatter_kernel<<<(EE + NN + 255) / 256, 256>>>(ei);
    segstart_kernel<<<1, GG + 1>>>(bat);
    convert_w_kernel<<<(DD * HH + HH * HH + 255) / 256, 256>>>(W1, W2);
    build_csr_kernel<<<NN / 8, 256>>>();
    convert_x_kernel<<<2048, 256>>>(x);
    agg1_kernel<<<NN / 8, 256>>>();
    hgemm_kernel<DD, true, true><<<dim3(2, 128), 256>>>(agg1h, w1h, b1, nullptr, hd1h);
    agg2_kernel<<<NN / 8, 256>>>();
    hgemm_kernel<HH, false, false><<<dim3(2, 128), 256>>>(agg2h, w2h, b2, h2, nullptr);
    pool_classify_kernel<<<GG, 256>>>(Wc, bc, out);
}

// round 5
// speedup vs baseline: 1.9919x; 1.1020x over previous
#include <cuda_runtime.h>
#include <cuda_fp16.h>
#include <stdint.h>

#define NN      16384
#define EE      524288
#define DD      128
#define HH      256
#define CC      10
#define GG      64
#define WPR     512          // bitmask words per row (16384/32)
#define CAP     160          // max neighbors per row

// ---------------- scratch (device globals; no allocation allowed) ----------------
__device__ uint32_t g_bm[(size_t)NN * WPR];        // 32 MB adjacency bitmask
__device__ int      g_nbr[(size_t)NN * CAP];       // CSR neighbor lists (unordered)
__device__ int      g_cnt[NN];                     // per-row neighbor counters
__device__ float    g_dis[NN];
__device__ __half   g_xh   [(size_t)NN * DD];      // half(dis[j]*x[j])
__device__ __half   g_agg1h[(size_t)NN * DD];
__device__ __half   g_hd1h [(size_t)NN * HH];      // half(dis*relu(.@W1+b1))
__device__ __half   g_agg2h[(size_t)NN * HH];
__device__ __half   g_h2h  [(size_t)NN * HH];      // half(relu(.@W2+b2))
__device__ __half   g_w1h[DD * HH];
__device__ __half   g_w2h[HH * HH];
__device__ int      g_segstart[GG + 1];

// ---------------- mma helpers ----------------
__device__ __forceinline__ uint32_t cvta_smem(const void* p) {
    return static_cast<uint32_t>(__cvta_generic_to_shared(p));
}
__device__ __forceinline__ void ldsm_x4(uint32_t (&r)[4], uint32_t addr) {
    asm volatile("ldmatrix.sync.aligned.m8n8.x4.shared.b16 {%0,%1,%2,%3}, [%4];"
                 : "=r"(r[0]), "=r"(r[1]), "=r"(r[2]), "=r"(r[3]) : "r"(addr));
}
__device__ __forceinline__ void ldsm_x4_t(uint32_t (&r)[4], uint32_t addr) {
    asm volatile("ldmatrix.sync.aligned.m8n8.x4.trans.shared.b16 {%0,%1,%2,%3}, [%4];"
                 : "=r"(r[0]), "=r"(r[1]), "=r"(r[2]), "=r"(r[3]) : "r"(addr));
}
__device__ __forceinline__ void mma16816(float (&d)[4], const uint32_t (&a)[4],
                                         const uint32_t b0, const uint32_t b1) {
    asm volatile("mma.sync.aligned.m16n8k16.row.col.f32.f16.f16.f32 "
                 "{%0,%1,%2,%3},{%4,%5,%6,%7},{%8,%9},{%0,%1,%2,%3};"
                 : "+f"(d[0]), "+f"(d[1]), "+f"(d[2]), "+f"(d[3])
                 : "r"(a[0]), "r"(a[1]), "r"(a[2]), "r"(a[3]), "r"(b0), "r"(b1));
}

// ---------------- fused init: zero bitmask + counters, convert weights, segstart ----------------
__global__ void init_kernel(const float* __restrict__ W1, const float* __restrict__ W2,
                            const int* __restrict__ batch) {
    int gidx = blockIdx.x * blockDim.x + threadIdx.x;   // 524288 threads
    const int n4 = NN * WPR / 4;
    uint4 z = make_uint4(0, 0, 0, 0);
    for (int i = gidx; i < n4; i += gridDim.x * blockDim.x)
        reinterpret_cast<uint4*>(g_bm)[i] = z;
    if (gidx < DD * HH) g_w1h[gidx] = __float2half_rn(W1[gidx]);
    if (gidx < HH * HH) g_w2h[gidx] = __float2half_rn(W2[gidx]);
    if (gidx < NN) g_cnt[gidx] = 0;
    int g = gidx - 100000;
    if (g >= 0 && g <= GG) {
        if (g == GG) { g_segstart[GG] = NN; }
        else {
            int lo = 0, hi = NN;
            while (lo < hi) {
                int mid = (lo + hi) >> 1;
                if (batch[mid] < g) lo = mid + 1; else hi = mid;
            }
            g_segstart[g] = lo;
        }
    }
}

// ---------------- scatter + direct CSR build (dedup via atomicOr old-value) ----------------
__global__ void scatter_build_kernel(const int* __restrict__ ei) {
    int idx = blockIdx.x * blockDim.x + threadIdx.x;
    int s, d;
    if (idx < EE) {
        s = ei[idx];
        d = ei[EE + idx];
    } else if (idx < EE + NN) {
        s = idx - EE; d = s;          // self-loop
    } else return;
    uint32_t bit = 1u << (d & 31);
    uint32_t old = atomicOr(&g_bm[(size_t)s * WPR + (d >> 5)], bit);
    if (!(old & bit)) {
        int pos = atomicAdd(&g_cnt[s], 1);
        if (pos < CAP) g_nbr[(size_t)s * CAP + pos] = d;
    }
}

// dis[n] = rsqrt(cnt[n]);  xh[n][f] = half(dis[n]*x[n][f])
__global__ void finalize_x_kernel(const float* __restrict__ x) {
    const int n2 = NN * DD / 2;
    const float2* x2 = reinterpret_cast<const float2*>(x);
    __half2* o2 = reinterpret_cast<__half2*>(g_xh);
    for (int i = blockIdx.x * blockDim.x + threadIdx.x; i < n2; i += gridDim.x * blockDim.x) {
        int row = i >> 6;
        int c = g_cnt[row];
        float s = rsqrtf((float)(c < 1 ? 1 : c));
        if ((i & 63) == 0) g_dis[row] = s;
        float2 v = x2[i];
        o2[i] = __float22half2_rn(make_float2(v.x * s, v.y * s));
    }
}

// ---------------- gathers ----------------

// warp per row, D=128: lane handles 4 halves; output fp16
__global__ void agg1_kernel() {
    int row  = (blockIdx.x * blockDim.x + threadIdx.x) >> 5;
    int lane = threadIdx.x & 31;
    if (row >= NN) return;
    const int* nbr = g_nbr + (size_t)row * CAP;
    int cnt = min(g_cnt[row], CAP);
    float4 acc = make_float4(0.f, 0.f, 0.f, 0.f);
    for (int t0 = 0; t0 < cnt; t0 += 32) {
        int j = (t0 + lane < cnt) ? nbr[t0 + lane] : 0;
        int m = min(32, cnt - t0);
        for (int k = 0; k < m; k++) {
            int jj = __shfl_sync(0xFFFFFFFFu, j, k);
            uint2 raw = *reinterpret_cast<const uint2*>(g_xh + (size_t)jj * DD + lane * 4);
            float2 f0 = __half22float2(*reinterpret_cast<__half2*>(&raw.x));
            float2 f1 = __half22float2(*reinterpret_cast<__half2*>(&raw.y));
            acc.x += f0.x; acc.y += f0.y; acc.z += f1.x; acc.w += f1.y;
        }
    }
    float s = g_dis[row];
    __half2 h0 = __float22half2_rn(make_float2(acc.x * s, acc.y * s));
    __half2 h1 = __float22half2_rn(make_float2(acc.z * s, acc.w * s));
    uint2 packed = make_uint2(*reinterpret_cast<uint32_t*>(&h0), *reinterpret_cast<uint32_t*>(&h1));
    *reinterpret_cast<uint2*>(g_agg1h + (size_t)row * DD + lane * 4) = packed;
}

// warp per row, H=256: lane handles 8 halves; output fp16
__global__ void agg2_kernel() {
    int row  = (blockIdx.x * blockDim.x + threadIdx.x) >> 5;
    int lane = threadIdx.x & 31;
    if (row >= NN) return;
    const int* nbr = g_nbr + (size_t)row * CAP;
    int cnt = min(g_cnt[row], CAP);
    float4 a0 = make_float4(0.f, 0.f, 0.f, 0.f);
    float4 a1 = make_float4(0.f, 0.f, 0.f, 0.f);
    for (int t0 = 0; t0 < cnt; t0 += 32) {
        int j = (t0 + lane < cnt) ? nbr[t0 + lane] : 0;
        int m = min(32, cnt - t0);
        for (int k = 0; k < m; k++) {
            int jj = __shfl_sync(0xFFFFFFFFu, j, k);
            uint4 raw = *reinterpret_cast<const uint4*>(g_hd1h + (size_t)jj * HH + lane * 8);
            float2 f0 = __half22float2(*reinterpret_cast<__half2*>(&raw.x));
            float2 f1 = __half22float2(*reinterpret_cast<__half2*>(&raw.y));
            float2 f2 = __half22float2(*reinterpret_cast<__half2*>(&raw.z));
            float2 f3 = __half22float2(*reinterpret_cast<__half2*>(&raw.w));
            a0.x += f0.x; a0.y += f0.y; a0.z += f1.x; a0.w += f1.y;
            a1.x += f2.x; a1.y += f2.y; a1.z += f3.x; a1.w += f3.y;
        }
    }
    float s = g_dis[row];
    __half2 h0 = __float22half2_rn(make_float2(a0.x * s, a0.y * s));
    __half2 h1 = __float22half2_rn(make_float2(a0.z * s, a0.w * s));
    __half2 h2 = __float22half2_rn(make_float2(a1.x * s, a1.y * s));
    __half2 h3 = __float22half2_rn(make_float2(a1.z * s, a1.w * s));
    uint4 packed = make_uint4(*reinterpret_cast<uint32_t*>(&h0), *reinterpret_cast<uint32_t*>(&h1),
                              *reinterpret_cast<uint32_t*>(&h2), *reinterpret_cast<uint32_t*>(&h3));
    *reinterpret_cast<uint4*>(g_agg2h + (size_t)row * HH + lane * 8) = packed;
}

// ---------------- HMMA GEMM: 128x128 CTA tile, 8 warps (32x64 each), BK=32 ----------------
template <int K, bool SCALE>
__global__ void __launch_bounds__(256, 2) hgemm_kernel(const __half* __restrict__ A,
                                                       const __half* __restrict__ W,
                                                       const float* __restrict__ bias,
                                                       __half* __restrict__ Ch) {
    __shared__ __half As[128][40];
    __shared__ __half Bs[32][136];

    const int tid  = threadIdx.x;
    const int lane = tid & 31;
    const int warp = tid >> 5;
    const int wm = warp & 3;
    const int wn = warp >> 2;
    const int rowBase = blockIdx.y * 128;
    const int colBase = blockIdx.x * 128;

    float acc[2][8][4];
    #pragma unroll
    for (int f = 0; f < 2; f++)
        #pragma unroll
        for (int t = 0; t < 8; t++)
            #pragma unroll
            for (int c = 0; c < 4; c++) acc[f][t][c] = 0.f;

    const int ar = tid >> 1, ac = (tid & 1) * 16;
    const int br = tid >> 3, bc = (tid & 7) * 16;

    for (int k0 = 0; k0 < K; k0 += 32) {
        const __half* ag = A + (size_t)(rowBase + ar) * K + k0 + ac;
        *reinterpret_cast<uint4*>(&As[ar][ac])     = *reinterpret_cast<const uint4*>(ag);
        *reinterpret_cast<uint4*>(&As[ar][ac + 8]) = *reinterpret_cast<const uint4*>(ag + 8);
        const __half* bg = W + (size_t)(k0 + br) * 256 + colBase + bc;
        *reinterpret_cast<uint4*>(&Bs[br][bc])     = *reinterpret_cast<const uint4*>(bg);
        *reinterpret_cast<uint4*>(&Bs[br][bc + 8]) = *reinterpret_cast<const uint4*>(bg + 8);
        __syncthreads();

        #pragma unroll
        for (int kk = 0; kk < 32; kk += 16) {
            uint32_t afr[2][4];
            #pragma unroll
            for (int f = 0; f < 2; f++)
                ldsm_x4(afr[f], cvta_smem(&As[wm * 32 + f * 16 + (lane & 15)][kk + (lane >> 4) * 8]));
            uint32_t bfr[8][2];
            #pragma unroll
            for (int g = 0; g < 4; g++) {
                uint32_t t4[4];
                ldsm_x4_t(t4, cvta_smem(&Bs[kk + (lane & 15)][wn * 64 + g * 16 + (lane >> 4) * 8]));
                bfr[2 * g][0] = t4[0]; bfr[2 * g][1] = t4[1];
                bfr[2 * g + 1][0] = t4[2]; bfr[2 * g + 1][1] = t4[3];
            }
            #pragma unroll
            for (int f = 0; f < 2; f++)
                #pragma unroll
                for (int t = 0; t < 8; t++)
                    mma16816(acc[f][t], afr[f], bfr[t][0], bfr[t][1]);
        }
        __syncthreads();
    }

    #pragma unroll
    for (int f = 0; f < 2; f++) {
        #pragma unroll
        for (int t = 0; t < 8; t++) {
            int r0  = rowBase + wm * 32 + f * 16 + (lane >> 2);
            int col = colBase + wn * 64 + t * 8 + (lane & 3) * 2;
            float b0 = bias[col], b1 = bias[col + 1];
            #pragma unroll
            for (int h = 0; h < 2; h++) {
                int row = r0 + h * 8;
                float v0 = fmaxf(acc[f][t][h * 2 + 0] + b0, 0.f);
                float v1 = fmaxf(acc[f][t][h * 2 + 1] + b1, 0.f);
                if (SCALE) { float s = g_dis[row]; v0 *= s; v1 *= s; }
                *reinterpret_cast<__half2*>(Ch + (size_t)row * 256 + col) =
                    __float22half2_rn(make_float2(v0, v1));
            }
        }
    }
}

// ---------------- pooling / classifier ----------------
__global__ void __launch_bounds__(256) pool_classify_kernel(const float* __restrict__ Wc,
                                                            const float* __restrict__ bc,
                                                            float* __restrict__ out) {
    int g = blockIdx.x;
    int t = threadIdx.x;
    int s = g_segstart[g], e = g_segstart[g + 1];
    float sum = 0.f;
    for (int n = s; n < e; n++) sum += __half2float(g_h2h[(size_t)n * HH + t]);
    float cnt = (float)max(e - s, 1);
    float pv = sum / cnt;

    float part[CC];
    const float* wr = Wc + t * CC;
    #pragma unroll
    for (int c = 0; c < CC; c++) part[c] = pv * wr[c];
    #pragma unroll
    for (int o = 16; o > 0; o >>= 1)
        #pragma unroll
        for (int c = 0; c < CC; c++) part[c] += __shfl_down_sync(0xFFFFFFFFu, part[c], o);

    __shared__ float red[8][CC];
    if ((t & 31) == 0)
        #pragma unroll
        for (int c = 0; c < CC; c++) red[t >> 5][c] = part[c];
    __syncthreads();
    if (t < CC) {
        float o = bc[t];
        #pragma unroll
        for (int w = 0; w < 8; w++) o += red[w][t];
        out[g * CC + t] = o;
    }
}

// ---------------- launch ----------------
extern "C" void kernel_launch(void* const* d_in, const int* in_sizes, int n_in,
                              void* d_out, int out_size) {
    const float* x   = (const float*)d_in[0];
    const int*   ei  = (const int*)  d_in[1];
    const int*   bat = (const int*)  d_in[2];
    const float* W1  = (const float*)d_in[3];
    const float* b1  = (const float*)d_in[4];
    const float* W2  = (const float*)d_in[5];
    const float* b2  = (const float*)d_in[6];
    const float* Wc  = (const float*)d_in[7];
    const float* bc  = (const float*)d_in[8];
    float* out = (float*)d_out;

    __half *w1h, *w2h, *agg1h, *agg2h, *hd1h, *h2h;
    cudaGetSymbolAddress((void**)&w1h,   g_w1h);
    cudaGetSymbolAddress((void**)&w2h,   g_w2h);
    cudaGetSymbolAddress((void**)&agg1h, g_agg1h);
    cudaGetSymbolAddress((void**)&agg2h, g_agg2h);
    cudaGetSymbolAddress((void**)&hd1h,  g_hd1h);
    cudaGetSymbolAddress((void**)&h2h,   g_h2h);

    init_kernel<<<2048, 256>>>(W1, W2, bat);
    scatter_build_kernel<<<(EE + NN + 255) / 256, 256>>>(ei);
    finalize_x_kernel<<<2048, 256>>>(x);
    agg1_kernel<<<NN / 8, 256>>>();
    hgemm_kernel<DD, true><<<dim3(2, 128), 256>>>(agg1h, w1h, b1, hd1h);
    agg2_kernel<<<NN / 8, 256>>>();
    hgemm_kernel<HH, false><<<dim3(2, 128), 256>>>(agg2h, w2h, b2, h2h);
    pool_classify_kernel<<<GG, 256>>>(Wc, bc, out);
}